// round 1
// baseline (speedup 1.0000x reference)
#include <cuda_runtime.h>
#include <math.h>

#define Bb 32
#define Tt 1024
#define Dd 256
#define BT (Bb*Tt)
#define MAXE 64
#define LN_EPS 1e-5f
#define EPS_ADJ 1e-6f

// ---------------- device scratch (static, allocation-free) ----------------
__device__ float    g_xn[BT*Dd];        // normalized x
__device__ float    g_s0[BT*Dd];        // scratch ping
__device__ float    g_s1[BT*Dd];        // scratch pong
__device__ float    g_mf[BT];           // mask as float
__device__ int      g_top2[BT*2];       // top-2 indices per row
__device__ unsigned g_bits[BT*(Tt/32)]; // adjacency bitmap (T bits per row)
__device__ float    g_rinv[BT];         // 1/sqrt(rowsum+eps)
__device__ int      g_ecols[BT*MAXE];
__device__ float    g_evals[BT*MAXE];
__device__ int      g_ecnt[BT];

// ---------------- row normalize + mask cast ----------------
__global__ void k_normalize(const float* __restrict__ x, const int* __restrict__ mask) {
    int row = blockIdx.x;
    int d = threadIdx.x;
    float v = x[row*Dd + d];
    __shared__ float red[8];
    float ss = v*v;
    #pragma unroll
    for (int o = 16; o; o >>= 1) ss += __shfl_xor_sync(~0u, ss, o);
    if ((threadIdx.x & 31) == 0) red[threadIdx.x >> 5] = ss;
    __syncthreads();
    if (threadIdx.x < 8) {
        float t = red[threadIdx.x];
        #pragma unroll
        for (int o = 4; o; o >>= 1) t += __shfl_xor_sync(0xff, t, o);
        if (threadIdx.x == 0) red[0] = t;
    }
    __syncthreads();
    float nrm = sqrtf(red[0]);
    float rn = 1.f / fmaxf(nrm, 1e-12f);
    g_xn[row*Dd + d] = v * rn;
    if (d == 0) g_mf[row] = (float)mask[row];
}

// ---------------- fused sim row-panel GEMM + streamed top-2 ----------------
#define TI 64
#define TJ 64
#define KT 16

__global__ __launch_bounds__(256) void k_simtop2() {
    int b = blockIdx.y;
    int i0 = blockIdx.x * TI;
    int rowbase = b * Tt;
    __shared__ float As[KT][TI+4];
    __shared__ float Bs[KT][TJ+4];
    __shared__ float smask[TJ];
    __shared__ float rmask[TI];
    __shared__ float cv[TI*32];
    __shared__ int   ci[TI*32];

    int tid = threadIdx.x;
    int tx = tid & 15, ty = tid >> 4;

    float v1[4], v2[4]; int j1[4], j2[4];
    #pragma unroll
    for (int r = 0; r < 4; r++) { v1[r] = -1e30f; v2[r] = -1e30f; j1[r] = 0; j2[r] = 0; }

    if (tid < TI) rmask[tid] = g_mf[rowbase + i0 + tid];

    int lrow = tid >> 2;
    int lk4  = (tid & 3) * 4;

    for (int j0 = 0; j0 < Tt; j0 += TJ) {
        __syncthreads();   // previous epilogue done with smask
        if (tid < TJ) smask[tid] = g_mf[rowbase + j0 + tid];

        float acc[4][4];
        #pragma unroll
        for (int r = 0; r < 4; r++)
            #pragma unroll
            for (int c = 0; c < 4; c++) acc[r][c] = 0.f;

        for (int k0 = 0; k0 < Dd; k0 += KT) {
            __syncthreads();
            {
                const float4 a  = *(const float4*)&g_xn[(rowbase + i0 + lrow)*Dd + k0 + lk4];
                As[lk4+0][lrow] = a.x;  As[lk4+1][lrow] = a.y;
                As[lk4+2][lrow] = a.z;  As[lk4+3][lrow] = a.w;
                const float4 bq = *(const float4*)&g_xn[(rowbase + j0 + lrow)*Dd + k0 + lk4];
                Bs[lk4+0][lrow] = bq.x; Bs[lk4+1][lrow] = bq.y;
                Bs[lk4+2][lrow] = bq.z; Bs[lk4+3][lrow] = bq.w;
            }
            __syncthreads();
            #pragma unroll
            for (int k = 0; k < KT; k++) {
                float4 av = *(const float4*)&As[k][ty*4];
                float4 bv = *(const float4*)&Bs[k][tx*4];
                float ar[4] = {av.x, av.y, av.z, av.w};
                float br[4] = {bv.x, bv.y, bv.z, bv.w};
                #pragma unroll
                for (int r = 0; r < 4; r++)
                    #pragma unroll
                    for (int c = 0; c < 4; c++)
                        acc[r][c] = fmaf(ar[r], br[c], acc[r][c]);
            }
        }
        // epilogue: masked sim, diag = -1, update running top-2
        #pragma unroll
        for (int r = 0; r < 4; r++) {
            int gi = i0 + ty*4 + r;
            float mi = rmask[ty*4 + r];
            #pragma unroll
            for (int c = 0; c < 4; c++) {
                int gj = j0 + tx*4 + c;
                float s = acc[r][c] * mi * smask[tx*4 + c];
                if (gj == gi) s = -1.0f;
                if (s > v1[r])      { v2[r]=v1[r]; j2[r]=j1[r]; v1[r]=s; j1[r]=gj; }
                else if (s > v2[r]) { v2[r]=s; j2[r]=gj; }
            }
        }
    }
    // merge candidates across the 16 threads sharing each row
    __syncthreads();
    #pragma unroll
    for (int r = 0; r < 4; r++) {
        int row = ty*4 + r;
        cv[row*32 + tx*2 + 0] = v1[r]; ci[row*32 + tx*2 + 0] = j1[r];
        cv[row*32 + tx*2 + 1] = v2[r]; ci[row*32 + tx*2 + 1] = j2[r];
    }
    __syncthreads();
    if (tid < TI) {
        float b1 = -1e30f, b2 = -1e30f; int x1 = 0, x2 = 0;
        for (int c = 0; c < 32; c++) {
            float v = cv[tid*32 + c]; int j = ci[tid*32 + c];
            if ((v > b1) || (v == b1 && j < x1)) { b2=b1; x2=x1; b1=v; x1=j; }
            else if ((v > b2) || (v == b2 && j < x2)) { b2=v; x2=j; }
        }
        int grow = rowbase + i0 + tid;
        g_top2[grow*2 + 0] = x1;
        g_top2[grow*2 + 1] = x2;
    }
}

// ---------------- adjacency bitmap ----------------
__global__ void k_clear() {
    int i = blockIdx.x*256 + threadIdx.x;
    if (i < BT*(Tt/32)) g_bits[i] = 0u;
}

__global__ void k_setbits() {
    int row = blockIdx.x*256 + threadIdx.x;
    if (row >= BT) return;
    int b = row / Tt, i = row % Tt;
    unsigned* wb = &g_bits[row*(Tt/32)];
    atomicOr(&wb[i >> 5], 1u << (i & 31));
    if (i > 0)      atomicOr(&wb[(i-1) >> 5], 1u << ((i-1) & 31));
    if (i < Tt-1)   atomicOr(&wb[(i+1) >> 5], 1u << ((i+1) & 31));
    float mi = g_mf[row];
    #pragma unroll
    for (int t = 0; t < 2; t++) {
        int j = g_top2[row*2 + t];
        float mj = g_mf[b*Tt + j];
        if (mi*mj != 0.f) {
            atomicOr(&wb[j >> 5], 1u << (j & 31));
            atomicOr(&g_bits[(b*Tt + j)*(Tt/32) + (i >> 5)], 1u << (i & 31));
        }
    }
}

// ---------------- edge extraction: sim values + row sums (warp per row) ----------------
__global__ __launch_bounds__(256) void k_edges() {
    int warp = (blockIdx.x*256 + threadIdx.x) >> 5;
    int lane = threadIdx.x & 31;
    if (warp >= BT) return;
    int row = warp;
    int b = row / Tt, i = row % Tt;
    float a[8];
    #pragma unroll
    for (int u = 0; u < 8; u++) a[u] = g_xn[row*Dd + lane + 32*u];
    float mi = g_mf[row];
    float rowsum = 0.f;
    int cnt = 0;
    for (int w = 0; w < Tt/32; w++) {
        unsigned bitsw = g_bits[row*(Tt/32) + w];
        while (bitsw) {
            int bit = __ffs(bitsw) - 1;
            bitsw &= bitsw - 1;
            int j = w*32 + bit;
            int jr = b*Tt + j;
            float dot = 0.f;
            #pragma unroll
            for (int u = 0; u < 8; u++) dot = fmaf(a[u], g_xn[jr*Dd + lane + 32*u], dot);
            #pragma unroll
            for (int o = 16; o; o >>= 1) dot += __shfl_xor_sync(~0u, dot, o);
            float val = dot * mi * g_mf[jr];
            if (j == i) val += 1.0f;        // + eye (pre-normalization)
            rowsum += val;
            if (lane == 0 && cnt < MAXE) {
                g_ecols[row*MAXE + cnt] = j;
                g_evals[row*MAXE + cnt] = val;
            }
            cnt++;
        }
    }
    if (lane == 0) {
        g_ecnt[row] = min(cnt, MAXE);
        g_rinv[row] = rsqrtf(rowsum + EPS_ADJ);
    }
}

// ---------------- sparse adj @ h ----------------
__global__ __launch_bounds__(256) void k_spmm(const float* __restrict__ hin,
                                              float* __restrict__ hout) {
    int row = blockIdx.x;
    int d = threadIdx.x;
    int b = row / Tt;
    int cnt = g_ecnt[row];
    float ri = g_rinv[row], mi = g_mf[row];
    float acc = 0.f;
    for (int e = 0; e < cnt; e++) {
        int j = g_ecols[row*MAXE + e];
        int jr = b*Tt + j;
        float w = g_evals[row*MAXE + e] * ri * g_rinv[jr] * mi * g_mf[jr];
        acc = fmaf(w, hin[jr*Dd + d], acc);
    }
    hout[row*Dd + d] = acc;
}

// ---------------- dense h @ W^T + bias, ELU fused ----------------
__global__ __launch_bounds__(256) void k_gemm_bias_elu(const float* __restrict__ A,
                                                       const float* __restrict__ W,
                                                       const float* __restrict__ bias,
                                                       float* __restrict__ out) {
    int r0 = blockIdx.x * 64;
    int o0 = blockIdx.y * 64;
    __shared__ float As[KT][68];
    __shared__ float Bs[KT][68];
    int tid = threadIdx.x;
    int tx = tid & 15, ty = tid >> 4;
    int lrow = tid >> 2;
    int lk4  = (tid & 3) * 4;

    float acc[4][4];
    #pragma unroll
    for (int r = 0; r < 4; r++)
        #pragma unroll
        for (int c = 0; c < 4; c++) acc[r][c] = 0.f;

    for (int k0 = 0; k0 < Dd; k0 += KT) {
        __syncthreads();
        {
            const float4 a  = *(const float4*)&A[(r0 + lrow)*Dd + k0 + lk4];
            As[lk4+0][lrow] = a.x;  As[lk4+1][lrow] = a.y;
            As[lk4+2][lrow] = a.z;  As[lk4+3][lrow] = a.w;
            const float4 bq = *(const float4*)&W[(o0 + lrow)*Dd + k0 + lk4];
            Bs[lk4+0][lrow] = bq.x; Bs[lk4+1][lrow] = bq.y;
            Bs[lk4+2][lrow] = bq.z; Bs[lk4+3][lrow] = bq.w;
        }
        __syncthreads();
        #pragma unroll
        for (int k = 0; k < KT; k++) {
            float4 av = *(const float4*)&As[k][ty*4];
            float4 bv = *(const float4*)&Bs[k][tx*4];
            float ar[4] = {av.x, av.y, av.z, av.w};
            float br[4] = {bv.x, bv.y, bv.z, bv.w};
            #pragma unroll
            for (int r = 0; r < 4; r++)
                #pragma unroll
                for (int c = 0; c < 4; c++)
                    acc[r][c] = fmaf(ar[r], br[c], acc[r][c]);
        }
    }
    #pragma unroll
    for (int r = 0; r < 4; r++) {
        int grow = r0 + ty*4 + r;
        #pragma unroll
        for (int c = 0; c < 4; c++) {
            int o = o0 + tx*4 + c;
            float v = acc[r][c] + bias[o];
            v = (v > 0.f) ? v : expm1f(v);   // ELU
            out[grow*Dd + o] = v;
        }
    }
}

// ---------------- LayerNorm over D ----------------
__global__ void k_ln(const float* __restrict__ in, const float* __restrict__ g,
                     const float* __restrict__ be, float* __restrict__ out) {
    int row = blockIdx.x;
    int d = threadIdx.x;
    float v = in[row*Dd + d];
    __shared__ float red[8];

    float s = v;
    #pragma unroll
    for (int o = 16; o; o >>= 1) s += __shfl_xor_sync(~0u, s, o);
    if ((threadIdx.x & 31) == 0) red[threadIdx.x >> 5] = s;
    __syncthreads();
    if (threadIdx.x < 8) {
        float t = red[threadIdx.x];
        #pragma unroll
        for (int o = 4; o; o >>= 1) t += __shfl_xor_sync(0xff, t, o);
        if (threadIdx.x == 0) red[0] = t;
    }
    __syncthreads();
    float mu = red[0] * (1.f/Dd);
    __syncthreads();

    float dv = v - mu;
    float s2 = dv*dv;
    #pragma unroll
    for (int o = 16; o; o >>= 1) s2 += __shfl_xor_sync(~0u, s2, o);
    if ((threadIdx.x & 31) == 0) red[threadIdx.x >> 5] = s2;
    __syncthreads();
    if (threadIdx.x < 8) {
        float t = red[threadIdx.x];
        #pragma unroll
        for (int o = 4; o; o >>= 1) t += __shfl_xor_sync(0xff, t, o);
        if (threadIdx.x == 0) red[0] = t;
    }
    __syncthreads();
    float var = red[0] * (1.f/Dd);
    out[row*Dd + d] = dv * rsqrtf(var + LN_EPS) * g[d] + be[d];
}

// ---------------- launch ----------------
extern "C" void kernel_launch(void* const* d_in, const int* in_sizes, int n_in,
                              void* d_out, int out_size) {
    const float* x    = (const float*)d_in[0];
    const int*   mask = (const int*)  d_in[1];
    const float* W0 = (const float*)d_in[2];
    const float* b0 = (const float*)d_in[3];
    const float* g0 = (const float*)d_in[4];
    const float* be0= (const float*)d_in[5];
    const float* W1 = (const float*)d_in[6];
    const float* b1 = (const float*)d_in[7];
    const float* g1 = (const float*)d_in[8];
    const float* be1= (const float*)d_in[9];
    float* out = (float*)d_out;

    float *s0, *s1;
    cudaGetSymbolAddress((void**)&s0, g_s0);
    cudaGetSymbolAddress((void**)&s1, g_s1);

    k_normalize<<<BT, 256>>>(x, mask);
    k_clear<<<(BT*(Tt/32) + 255)/256, 256>>>();
    k_simtop2<<<dim3(Tt/TI, Bb), 256>>>();
    k_setbits<<<BT/256, 256>>>();
    k_edges<<<(BT*32)/256, 256>>>();

    // layer 1
    k_spmm<<<BT, 256>>>(x, s0);
    k_gemm_bias_elu<<<dim3(BT/64, Dd/64), 256>>>(s0, W0, b0, s1);
    k_ln<<<BT, 256>>>(s1, g0, be0, s0);
    // layer 2
    k_spmm<<<BT, 256>>>(s0, s1);
    k_gemm_bias_elu<<<dim3(BT/64, Dd/64), 256>>>(s1, W1, b1, s0);
    k_ln<<<BT, 256>>>(s0, g1, be1, out);
}